// round 3
// baseline (speedup 1.0000x reference)
#include <cuda_runtime.h>
#include <math.h>

// Fixed shapes
#define B_   8
#define NQ_  1280
#define D_   256
#define CIN_ 64
#define H_   200
#define W_   200

// Roles: [0,64) conv stage A; [64,96) combine+GEMV stage B; ALL 256 blocks stream a slice
#define NBLK_A 64
#define NBLK_B 32
#define NTOT   256
#define F4_TOTAL   (B_ * NQ_ * (D_ / 4))   // 655360
#define F4_PER_BLK (F4_TOTAL / NTOT)       // 2560  (within ONE batch: 81920/2560=32)
#define F4_PER_THR (F4_PER_BLK / 256)      // 10

// Scratch + sync (no allocations allowed)
__device__ float g_part[B_][8][D_][4];   // conv partial sums per ci-chunk per corner
__device__ float g_r[B_][D_];            // per-batch residual row
__device__ unsigned int g_flagA;         // -> NBLK_A when stage A done (reset by last B blk)
__device__ unsigned int g_flagB;         // -> NBLK_B when stage B done (reset by last done blk)
__device__ unsigned int g_d1[8];         // hierarchical done counters
__device__ unsigned int g_d2;

__global__ __launch_bounds__(256) void fused_kernel(
    const float* __restrict__ queries,
    const float* __restrict__ navi,
    const float* __restrict__ bev,
    const float* __restrict__ point_score,
    const float* __restrict__ aws_w,
    const float* __restrict__ aws_b,
    const float* __restrict__ conv_w,
    const float* __restrict__ conv_b,
    const float* __restrict__ out_w,
    const float* __restrict__ out_b,
    float* __restrict__ out)
{
    const int blk = blockIdx.x;
    const int tid = threadIdx.x;

    if (blk < NBLK_A) {
        // ================= Stage A: 3x3 conv at the 4 bilinear corner pixels ======
        const int b     = blk >> 3;
        const int chunk = blk & 7;   // 8 input channels per chunk

        const float gx = (navi[2*b+1] * (1.0f/32.0f) + 1.0f) * (0.5f * W_) - 0.5f;
        const float gy = (navi[2*b+0] * (1.0f/32.0f) + 1.0f) * (0.5f * H_) - 0.5f;
        const int x0 = (int)floorf(gx);
        const int y0 = (int)floorf(gy);

        __shared__ float patch[8][16];   // 4x4 patch per local input channel
        if (tid < 128) {
            const int ci_l = tid >> 4, pos = tid & 15;
            const int iy = y0 - 1 + (pos >> 2);
            const int ix = x0 - 1 + (pos & 3);
            float v = 0.0f;   // zero padding
            if (iy >= 0 && iy < H_ && ix >= 0 && ix < W_)
                v = bev[((b * CIN_ + chunk * 8 + ci_l) * H_ + iy) * W_ + ix];
            patch[ci_l][pos] = v;
        }

        // Prefetch all 72 weights as 18 batched LDG.128
        const float4* __restrict__ wv =
            (const float4*)(conv_w + tid * (CIN_ * 9) + chunk * 72);
        float4 wq[18];
        #pragma unroll
        for (int j = 0; j < 18; j++) wq[j] = wv[j];
        const float* w = (const float*)wq;

        __syncthreads();

        float a0 = 0.f, a1 = 0.f, a2 = 0.f, a3 = 0.f;
        #pragma unroll
        for (int cl = 0; cl < 8; cl++) {
            float p[16];
            #pragma unroll
            for (int j = 0; j < 16; j++) p[j] = patch[cl][j];
            const float* wc = w + cl * 9;
            #pragma unroll
            for (int kh = 0; kh < 3; kh++)
                #pragma unroll
                for (int kw = 0; kw < 3; kw++) {
                    const float wvv = wc[kh * 3 + kw];
                    a0 = fmaf(wvv, p[(kh + 0) * 4 + (kw + 0)], a0);
                    a1 = fmaf(wvv, p[(kh + 0) * 4 + (kw + 1)], a1);
                    a2 = fmaf(wvv, p[(kh + 1) * 4 + (kw + 0)], a2);
                    a3 = fmaf(wvv, p[(kh + 1) * 4 + (kw + 1)], a3);
                }
        }
        *(float4*)&g_part[b][chunk][tid][0] = make_float4(a0, a1, a2, a3);
        __threadfence();           // release
        __syncthreads();
        if (tid == 0) atomicAdd(&g_flagA, 1);

    } else if (blk < NBLK_A + NBLK_B) {
        // ================= Stage B: bias+ReLU+bilinear+aws, then 256x256 GEMV =====
        const int blkB  = blk - NBLK_A;
        const int b     = blkB >> 2;            // batch
        const int rg    = blkB & 3;             // row-group (64 rows of out_w)
        const int row_l = tid >> 2;             // 0..63
        const int qq    = tid & 3;              // column quarter (64 cols)
        const int d     = rg * 64 + row_l;      // output row 0..255

        // Prefetch out_w segment BEFORE spinning (hides cold latency)
        const float4* __restrict__ wp = (const float4*)(out_w + d * D_ + qq * 64);
        float4 wreg[16];
        #pragma unroll
        for (int j = 0; j < 16; j++) wreg[j] = wp[j];
        const float ob = out_b[d];

        // Pre-spin: per-channel sine-embed term, conv bias, bilinear weights
        const int c = tid;
        const float v = (c < 128) ? point_score[2*b+1] : point_score[2*b+0];
        const int kk = (c & 127) >> 1;
        const float inv_t = exp2f(-(float)kk * (13.28771237954945f / 64.0f)); // 10000^{-kk/64}
        const float arg = v * 6.283185307179586f * inv_t;
        const float e = (c & 1) ? cosf(arg) : sinf(arg);
        const float awsterm = e * aws_w[c];
        const float awsbias = aws_b[0];
        const float cb = conv_b[c];

        const float gx = (navi[2*b+1] * (1.0f/32.0f) + 1.0f) * (0.5f * W_) - 0.5f;
        const float gy = (navi[2*b+0] * (1.0f/32.0f) + 1.0f) * (0.5f * H_) - 0.5f;
        const float x0f = floorf(gx), y0f = floorf(gy);
        const float wx1 = gx - x0f, wy1 = gy - y0f;
        const int x0 = (int)x0f, y0 = (int)y0f;
        float wt0 = (1.f - wx1) * (1.f - wy1);
        float wt1 = wx1 * (1.f - wy1);
        float wt2 = (1.f - wx1) * wy1;
        float wt3 = wx1 * wy1;
        if (!(x0   >= 0 && x0   < W_ && y0   >= 0 && y0   < H_)) wt0 = 0.f;
        if (!(x0+1 >= 0 && x0+1 < W_ && y0   >= 0 && y0   < H_)) wt1 = 0.f;
        if (!(x0   >= 0 && x0   < W_ && y0+1 >= 0 && y0+1 < H_)) wt2 = 0.f;
        if (!(x0+1 >= 0 && x0+1 < W_ && y0+1 >= 0 && y0+1 < H_)) wt3 = 0.f;

        asm volatile("" ::: "memory");   // keep prefetches issued before the spin

        __shared__ float red[D_];
        __shared__ float s_s[D_];
        __shared__ float s_part[D_];

        // Wait for conv partials: POLL WITH LOADS, not atomic RMWs
        if (tid == 0) {
            while (*(volatile unsigned int*)&g_flagA < NBLK_A) __nanosleep(64);
        }
        __syncthreads();
        __threadfence();   // acquire

        // aws = sineembed(point_score) . aws_w + aws_b
        red[tid] = awsterm;
        __syncthreads();
        #pragma unroll
        for (int s = 128; s > 0; s >>= 1) {
            if (tid < s) red[tid] += red[tid + s];
            __syncthreads();
        }
        const float aws = red[0] + awsbias;

        // finish conv at 4 corners (+bias, ReLU), bilinear combine, scale by aws
        float4 acc = make_float4(0.f, 0.f, 0.f, 0.f);
        #pragma unroll
        for (int ch = 0; ch < 8; ch++) {
            const float4 pp = *(const float4*)&g_part[b][ch][c][0];
            acc.x += pp.x; acc.y += pp.y; acc.z += pp.z; acc.w += pp.w;
        }
        const float v0 = fmaxf(acc.x + cb, 0.f);
        const float v1 = fmaxf(acc.y + cb, 0.f);
        const float v2 = fmaxf(acc.z + cb, 0.f);
        const float v3 = fmaxf(acc.w + cb, 0.f);
        s_s[c] = (wt0 * v0 + wt1 * v1 + wt2 * v2 + wt3 * v3) * aws;  // aw == 1
        __syncthreads();

        // GEMV quarter-row from preloaded registers
        const float* sseg = s_s + qq * 64;
        const float* wr = (const float*)wreg;
        float part = 0.f;
        #pragma unroll
        for (int j = 0; j < 64; j++) part = fmaf(wr[j], sseg[j], part);
        s_part[tid] = part;
        __syncthreads();
        if (qq == 0)
            g_r[b][d] = ob + s_part[tid] + s_part[tid+1] + s_part[tid+2] + s_part[tid+3];
        __threadfence();   // release
        __syncthreads();
        if (tid == 0) {
            const unsigned int t = atomicAdd(&g_flagB, 1);
            // last B block: all B blocks have passed the flagA spin -> safe to reset
            if (t == NBLK_B - 1) g_flagA = 0;
        }
    }

    // ================= Consumer slice: out = queries + r[b]  (ALL blocks) =========
    {
        const int base = blk * F4_PER_BLK + tid;          // slice lies in ONE batch
        const float4* __restrict__ q4 = (const float4*)queries;
        float4* __restrict__ o4 = (float4*)out;

        float4 a[F4_PER_THR];
        #pragma unroll
        for (int k = 0; k < F4_PER_THR; k++) a[k] = q4[base + k * 256];

        asm volatile("" ::: "memory");   // keep prefetches issued before the spin

        if (tid == 0) {
            while (*(volatile unsigned int*)&g_flagB < NBLK_B) __nanosleep(64);
        }
        __syncthreads();
        __threadfence();   // acquire

        // residual float4 for this thread: (base + k*256) & 63 == tid & 63; batch = blk>>5
        const float4 rv = ((const float4*)g_r)[(blk >> 5) * (D_ / 4) + (tid & 63)];
        #pragma unroll
        for (int k = 0; k < F4_PER_THR; k++) {
            float4 t = a[k];
            t.x += rv.x; t.y += rv.y; t.z += rv.z; t.w += rv.w;
            o4[base + k * 256] = t;
        }
    }

    // ---- hierarchical done counter; last block resets flagB (overlaps stores) ----
    __syncthreads();
    if (tid == 0) {
        const unsigned int t1 = atomicAdd(&g_d1[blk & 7], 1);
        if (t1 == (NTOT / 8) - 1) {
            const unsigned int t2 = atomicAdd(&g_d2, 1);
            if (t2 == 7) {
                g_flagB = 0;
                g_d2 = 0;
                #pragma unroll
                for (int j = 0; j < 8; j++) g_d1[j] = 0;
            }
        }
    }
}

extern "C" void kernel_launch(void* const* d_in, const int* in_sizes, int n_in,
                              void* d_out, int out_size) {
    const float* queries     = (const float*)d_in[0];
    const float* navi        = (const float*)d_in[1];
    const float* bev         = (const float*)d_in[2];
    // d_in[3] spatial_shape unused (H=W=200 fixed)
    const float* point_score = (const float*)d_in[4];
    // d_in[5] aw_w, d_in[6] aw_b dead: softmax over size-1 axis == 1
    const float* aws_w       = (const float*)d_in[7];
    const float* aws_b       = (const float*)d_in[8];
    const float* conv_w      = (const float*)d_in[9];
    const float* conv_b      = (const float*)d_in[10];
    const float* out_w       = (const float*)d_in[11];
    const float* out_b       = (const float*)d_in[12];

    fused_kernel<<<NTOT, 256>>>(queries, navi, bev, point_score,
                                aws_w, aws_b, conv_w, conv_b,
                                out_w, out_b, (float*)d_out);
}